// round 13
// baseline (speedup 1.0000x reference)
#include <cuda_runtime.h>

// Shapes fixed by reference setup_inputs
#define NTOK   16384      // B*T
#define DDIM   2048
#define NEXP   16
#define TOK_W  8          // tokens per warp (one group per warp)
#define NGRP   (NTOK / TOK_W)          // 2048 groups
#define GRID_MAIN 148
#define BLOCK_MAIN 448
#define WARPS_CTA 14
#define NHC    32         // half-chunks of 64 d
#define STAGES 3
#define STG_FLOATS 512    // 8 tok * 64 d floats = 2KB per stage

#define W2_U64      (NEXP * DDIM / 2)              // 16384 u64 = 128KB
#define XSTG_FLOATS (WARPS_CTA * STAGES * STG_FLOATS)

__device__ float g_zp[GRID_MAIN];     // per-CTA z-loss partials (deterministic)
__device__ unsigned int g_ctr;        // last-CTA ticket (reset each launch)

typedef unsigned long long u64;

__device__ __forceinline__ float fnoise(float x) {
    return copysignf(sqrtf(fabsf(x)), x);
}
__device__ __forceinline__ void ffma2(u64 &d, u64 a, u64 b) {
    asm("fma.rn.f32x2 %0, %1, %2, %0;" : "+l"(d) : "l"(a), "l"(b));
}
__device__ __forceinline__ u64 addx2(u64 a, u64 b) {
    u64 r; asm("add.rn.f32x2 %0, %1, %2;" : "=l"(r) : "l"(a), "l"(b)); return r;
}
__device__ __forceinline__ u64 pack2(float lo, float hi) {
    u64 r; asm("mov.b64 %0, {%1, %2};" : "=l"(r) : "f"(lo), "f"(hi)); return r;
}
__device__ __forceinline__ float2 unpack64(u64 v) {
    float2 r; asm("mov.b64 {%0, %1}, %2;" : "=f"(r.x), "=f"(r.y) : "l"(v)); return r;
}
__device__ __forceinline__ unsigned smem_u32(const void* p) {
    return (unsigned)__cvta_generic_to_shared(p);
}
__device__ __forceinline__ void cp16(unsigned dst, const float* src) {
    asm volatile("cp.async.cg.shared.global [%0], [%1], 16;"
                 :: "r"(dst), "l"(src) : "memory");
}
__device__ __forceinline__ void cp_commit() {
    asm volatile("cp.async.commit_group;" ::: "memory");
}
__device__ __forceinline__ void cp_wait2() {
    asm volatile("cp.async.wait_group 2;" ::: "memory");
}
__device__ __forceinline__ void cp_wait0() {
    asm volatile("cp.async.wait_group 0;" ::: "memory");
}

// ---------------------------------------------------------------------------
// d-parity-packed FFMA2 (ZERO packing MOVs in the mainloop).
//   acc[t][e] = packed f32x2 (sum over even d, sum over odd d).
//   a-operand: (x_d, x_{d+1}) straight out of x LDS.128 halves.
//   b-operand: (w_e[d], w_e[d+1]) pre-packed per expert in SMEM:
//     u64 idx(e,d): h=e>>3, e8=e&7, hc=d>>6, j=(d>>2)&15, k=(d>>1)&1
//                   -> hc*512 + h*256 + e8*32 + j*2 + k
//   Half-warp expert split: lanes 0-15 experts 0-7, lanes 16-31 experts 8-15;
//   both halves read the same x (smem broadcast).  8 tokens/warp, one group
//   per warp (2048 groups / 2072 warps).  x staged via depth-3 cp.async.
//   Epilogue: 16-lane butterfly, even+odd horizontal add, cross-half swap
//   through retired stage, per-lane top-2/softmax, fused last-CTA z-loss.
// ---------------------------------------------------------------------------
__global__ void __launch_bounds__(BLOCK_MAIN, 1)
router_kernel(const float* __restrict__ x,
              const float* __restrict__ w,  const float* __restrict__ sw,
              const float* __restrict__ b,  const float* __restrict__ sb,
              const float* __restrict__ ei, const float* __restrict__ eo,
              float* __restrict__ out) {
    extern __shared__ __align__(16) char smem_raw[];
    u64*   w2_s   = (u64*)smem_raw;                                  // 128KB
    float* xstage = (float*)(w2_s + W2_U64);                         // 84KB
    float* fi_s   = xstage + XSTG_FLOATS;                            // 2048
    float* fo_s   = fi_s + DDIM;                                     // 16
    float* b_s    = fo_s + NEXP;                                     // 16
    float* z_s    = b_s + NEXP;                                      // 14

    // --- noise factors ---
    for (int i = threadIdx.x; i < DDIM; i += BLOCK_MAIN) fi_s[i] = fnoise(ei[i]);
    if (threadIdx.x < NEXP) {
        float fo = fnoise(eo[threadIdx.x]);
        fo_s[threadIdx.x] = fo;
        b_s[threadIdx.x] = b[threadIdx.x] + sb[threadIdx.x] * fo;
    }
    __syncthreads();

    // --- noisy weights into d-pair-packed, expert-rowed, swizzled SMEM ---
    for (int it = threadIdx.x; it < NEXP * (DDIM / 2); it += BLOCK_MAIN) {
        int e = it >> 10;              // expert
        int d = (it & 1023) * 2;       // even d
        float2 wv = *(const float2*)(w  + e * DDIM + d);
        float2 sv = *(const float2*)(sw + e * DDIM + d);
        float2 fi = *(const float2*)(fi_s + d);
        float fo = fo_s[e];
        float a0 = wv.x + sv.x * fo * fi.x;
        float a1 = wv.y + sv.y * fo * fi.y;
        int h = e >> 3, e8 = e & 7;
        int hc = d >> 6, j = (d >> 2) & 15, k = (d >> 1) & 1;
        w2_s[hc * 512 + h * 256 + e8 * 32 + j * 2 + k] = pack2(a0, a1);
    }
    __syncthreads();

    const int lane = threadIdx.x & 31;
    const int wid  = threadIdx.x >> 5;
    const int gw   = blockIdx.x * WARPS_CTA + wid;   // group id == warp id
    const int j    = lane & 15;
    const int h    = lane >> 4;

    float* warp_stg = xstage + wid * (STAGES * STG_FLOATS);
    float* idx_out  = out + (size_t)NTOK * NEXP;

    if (gw < NGRP) {
        const int t0 = gw * TOK_W;
        const float* xg = x + (size_t)t0 * DDIM;
        unsigned stg_u32 = smem_u32(warp_stg);

        // prime 3 stages with half-chunks 0..2 (token split across halves)
        #pragma unroll
        for (int s = 0; s < STAGES; s++) {
            #pragma unroll
            for (int tp = 0; tp < 4; tp++)
                cp16(stg_u32 + s * 2048 + (tp * 2 + h) * 256 + j * 16,
                     xg + (tp * 2 + h) * DDIM + s * 64 + j * 4);
            cp_commit();
        }

        u64 acc[TOK_W][8];
        #pragma unroll
        for (int t = 0; t < TOK_W; t++)
            #pragma unroll
            for (int e8 = 0; e8 < 8; e8++) acc[t][e8] = 0ULL;

        int stage = 0;
        #pragma unroll 1
        for (int hc = 0; hc < NHC; hc++) {
            cp_wait2();   // half-chunk hc resident

            // hoist this half's w: 8 conflict-free LDS.128 -> 16 u64
            const u64* wb2 = w2_s + hc * 512 + h * 256 + j * 2;
            u64 wv[8][2];
            #pragma unroll
            for (int e8 = 0; e8 < 8; e8++) {
                ulonglong2 u = *(const ulonglong2*)(wb2 + e8 * 32);
                wv[e8][0] = u.x;   // (w[d], w[d+1])
                wv[e8][1] = u.y;   // (w[d+2], w[d+3])
            }

            const float* xs = warp_stg + stage * STG_FLOATS + j * 4;
            #pragma unroll
            for (int t = 0; t < TOK_W; t++) {
                ulonglong2 xu = *(const ulonglong2*)(xs + t * 64);
                #pragma unroll
                for (int e8 = 0; e8 < 8; e8++) {
                    ffma2(acc[t][e8], xu.x, wv[e8][0]);
                    ffma2(acc[t][e8], xu.y, wv[e8][1]);
                }
            }

            // refill this stage with half-chunk hc+3
            if (hc < NHC - STAGES) {
                #pragma unroll
                for (int tp = 0; tp < 4; tp++)
                    cp16(stg_u32 + stage * 2048 + (tp * 2 + h) * 256 + j * 16,
                         xg + (tp * 2 + h) * DDIM + (hc + 3) * 64 + j * 4);
            }
            cp_commit();   // uniform commit keeps wait_group algebra exact
            stage = (stage == STAGES - 1) ? 0 : stage + 1;
        }
        cp_wait0();   // drain before reusing the stage as scratch

        // butterfly within each 16-lane half, then even+odd horizontal add
        float fs[TOK_W][8];
        #pragma unroll
        for (int t = 0; t < TOK_W; t++)
            #pragma unroll
            for (int e8 = 0; e8 < 8; e8++) {
                u64 s = acc[t][e8];
                s = addx2(s, __shfl_xor_sync(0xffffffffu, s, 8));
                s = addx2(s, __shfl_xor_sync(0xffffffffu, s, 4));
                s = addx2(s, __shfl_xor_sync(0xffffffffu, s, 2));
                s = addx2(s, __shfl_xor_sync(0xffffffffu, s, 1));
                float2 q = unpack64(s);
                fs[t][e8] = q.x + q.y;
            }

        // cross-half exchange through this warp's retired stage memory
        float* red = warp_stg;           // 128 floats used
        if (j == 0) {
            #pragma unroll
            for (int t = 0; t < TOK_W; t++) {
                *(float4*)(red + h * 64 + t * 8 + 0) =
                    make_float4(fs[t][0], fs[t][1], fs[t][2], fs[t][3]);
                *(float4*)(red + h * 64 + t * 8 + 4) =
                    make_float4(fs[t][4], fs[t][5], fs[t][6], fs[t][7]);
            }
        }
        __syncwarp();

        const int town = lane >> 2;      // this lane's token
        const int q    = lane & 3;       // this lane's 4-expert output slice
        float v[NEXP];
        #pragma unroll
        for (int h2 = 0; h2 < 2; h2++)
            #pragma unroll
            for (int g2 = 0; g2 < 2; g2++) {
                float4 u = *(const float4*)(red + h2 * 64 + town * 8 + g2 * 4);
                v[h2 * 8 + g2 * 4 + 0] = u.x;
                v[h2 * 8 + g2 * 4 + 1] = u.y;
                v[h2 * 8 + g2 * 4 + 2] = u.z;
                v[h2 * 8 + g2 * 4 + 3] = u.w;
            }

        // top-2 + softmax + z for this lane's token
        float m1 = -1e30f, m2 = -1e30f;
        int i1 = 0, i2 = 0;
        #pragma unroll
        for (int e = 0; e < NEXP; e++) {
            float le = v[e] + b_s[e];
            if (le > m1)      { m2 = m1; i2 = i1; m1 = le; i1 = e; }
            else if (le > m2) { m2 = le; i2 = e; }
        }
        float ez = __expf(m2 - m1);
        float rz = 1.0f / (1.0f + ez);
        float p1 = rz, p2 = ez * rz;

        const int tok = t0 + town;
        const int e0 = q * 4;
        float4 o4;
        o4.x = (e0 + 0 == i1) ? p1 : ((e0 + 0 == i2) ? p2 : 0.0f);
        o4.y = (e0 + 1 == i1) ? p1 : ((e0 + 1 == i2) ? p2 : 0.0f);
        o4.z = (e0 + 2 == i1) ? p1 : ((e0 + 2 == i2) ? p2 : 0.0f);
        o4.w = (e0 + 3 == i1) ? p1 : ((e0 + 3 == i2) ? p2 : 0.0f);
        *(float4*)(out + (size_t)tok * NEXP + e0) = o4;
        if (q == 0)
            *(float2*)(idx_out + (size_t)tok * 2) =
                make_float2((float)i1, (float)i2);

        float lse = m1 + log1pf(ez);
        float zl = (q == 0) ? lse * lse : 0.0f;
        #pragma unroll
        for (int k = 16; k > 0; k >>= 1)
            zl += __shfl_xor_sync(0xffffffffu, zl, k);
        if (lane == 0) z_s[wid] = zl;
    } else {
        if (lane == 0) z_s[wid] = 0.0f;
    }

    // --- fused z-loss reduction: CTA partial, then last CTA finishes ---
    __syncthreads();
    __shared__ unsigned int s_last;
    if (threadIdx.x == 0) {
        float a = 0.0f;
        #pragma unroll
        for (int i = 0; i < WARPS_CTA; i++) a += z_s[i];
        g_zp[blockIdx.x] = a;
        __threadfence();
        unsigned int ticket = atomicAdd(&g_ctr, 1u);
        s_last = (ticket == GRID_MAIN - 1) ? 1u : 0u;
    }
    __syncthreads();
    if (s_last && wid == 0) {
        float a = 0.0f;
        for (int i = lane; i < GRID_MAIN; i += 32) a += __ldcg(&g_zp[i]);
        #pragma unroll
        for (int k = 16; k > 0; k >>= 1)
            a += __shfl_xor_sync(0xffffffffu, a, k);
        if (lane == 0) {
            out[(size_t)NTOK * NEXP + (size_t)NTOK * 2] = a * (1.0f / (float)NTOK);
            g_ctr = 0;   // reset for next launch / graph replay
        }
    }
}

// ---------------------------------------------------------------------------
extern "C" void kernel_launch(void* const* d_in, const int* in_sizes, int n_in,
                              void* d_out, int out_size) {
    const float* x  = (const float*)d_in[0];  // mh_output [4,4096,2048]
    const float* w  = (const float*)d_in[1];  // weight [16,2048]
    const float* sw = (const float*)d_in[2];  // sigma_weight
    const float* b  = (const float*)d_in[3];  // bias [16]
    const float* sb = (const float*)d_in[4];  // sigma_bias
    const float* ei = (const float*)d_in[5];  // eps_in [2048]
    const float* eo = (const float*)d_in[6];  // eps_out [16]
    float* out = (float*)d_out;

    const size_t smem_bytes = (size_t)W2_U64 * 8
                            + (size_t)XSTG_FLOATS * 4
                            + (size_t)(DDIM + 2 * NEXP + WARPS_CTA) * sizeof(float)
                            + 64;
    cudaFuncSetAttribute(router_kernel,
                         cudaFuncAttributeMaxDynamicSharedMemorySize,
                         (int)smem_bytes);
    router_kernel<<<GRID_MAIN, BLOCK_MAIN, smem_bytes>>>(x, w, sw, b, sb, ei, eo, out);
}

// round 14
// speedup vs baseline: 3.4859x; 3.4859x over previous
#include <cuda_runtime.h>

// Shapes fixed by reference setup_inputs
#define NTOK   16384      // B*T
#define DDIM   2048
#define NEXP   16
#define TOK_W  8          // tokens per warp (one group per warp)
#define NGRP   (NTOK / TOK_W)          // 2048 groups
#define GRID_MAIN 148
#define BLOCK_MAIN 448
#define WARPS_CTA 14
#define NHC    32         // half-chunks of 64 d
#define STAGES 3
#define STG_FLOATS 512    // 8 tok * 64 d floats = 2KB per stage

#define W2_U64      (NEXP * DDIM / 2)              // 16384 u64 = 128KB
#define XSTG_FLOATS (WARPS_CTA * STAGES * STG_FLOATS)

__device__ float g_zp[GRID_MAIN];     // per-CTA z-loss partials (deterministic)
__device__ unsigned int g_ctr;        // last-CTA ticket (reset each launch)

typedef unsigned long long u64;

__device__ __forceinline__ float fnoise(float x) {
    return copysignf(sqrtf(fabsf(x)), x);
}
__device__ __forceinline__ void ffma2(u64 &d, u64 a, u64 b) {
    asm("fma.rn.f32x2 %0, %1, %2, %0;" : "+l"(d) : "l"(a), "l"(b));
}
__device__ __forceinline__ u64 addx2(u64 a, u64 b) {
    u64 r; asm("add.rn.f32x2 %0, %1, %2;" : "=l"(r) : "l"(a), "l"(b)); return r;
}
__device__ __forceinline__ u64 pack2(float lo, float hi) {
    u64 r; asm("mov.b64 %0, {%1, %2};" : "=l"(r) : "f"(lo), "f"(hi)); return r;
}
__device__ __forceinline__ float2 unpack64(u64 v) {
    float2 r; asm("mov.b64 {%0, %1}, %2;" : "=f"(r.x), "=f"(r.y) : "l"(v)); return r;
}
__device__ __forceinline__ unsigned smem_u32(const void* p) {
    return (unsigned)__cvta_generic_to_shared(p);
}
__device__ __forceinline__ void cp16(unsigned dst, const float* src) {
    asm volatile("cp.async.cg.shared.global [%0], [%1], 16;"
                 :: "r"(dst), "l"(src) : "memory");
}
__device__ __forceinline__ void cp_commit() {
    asm volatile("cp.async.commit_group;" ::: "memory");
}
__device__ __forceinline__ void cp_wait2() {
    asm volatile("cp.async.wait_group 2;" ::: "memory");
}
__device__ __forceinline__ void cp_wait0() {
    asm volatile("cp.async.wait_group 0;" ::: "memory");
}

// ---------------------------------------------------------------------------
// Quarter-warp expert split + d-parity-packed FFMA2 (zero packing MOVs,
// 64-reg accumulators -> NO SPILLS).
//   Warp = 4 quarters (8 lanes).  Quarter q owns experts 4q..4q+3.
//   acc[t][el] = packed f32x2 (sum over even d, sum over odd d): 32 u64.
//   d window = 32 per pass: lane j=lane&7 covers d = wi*32 + 4j .. +3.
//   SMEM w (d-pair packed): u64 idx = wi*256 + el*64 + lane*2 + k
//     (wi = d>>5, el = e&3, lane = (e>>2)*8 + ((d>>2)&7), k = (d>>1)&1)
//   -> mainloop w read: ONE conflict-free LDS.128 per e_local per window.
//   x staged per warp via depth-3 cp.async (64-d half-chunks, 2KB stages);
//   x read is 4-way same-address broadcast across quarters (free).
//   Epilogue: 8-lane butterfly, even+odd horiz add, cross-quarter exchange
//   through retired stage, per-lane top-2/softmax, fused last-CTA z-loss.
// ---------------------------------------------------------------------------
__global__ void __launch_bounds__(BLOCK_MAIN, 1)
router_kernel(const float* __restrict__ x,
              const float* __restrict__ w,  const float* __restrict__ sw,
              const float* __restrict__ b,  const float* __restrict__ sb,
              const float* __restrict__ ei, const float* __restrict__ eo,
              float* __restrict__ out) {
    extern __shared__ __align__(16) char smem_raw[];
    u64*   w2_s   = (u64*)smem_raw;                                  // 128KB
    float* xstage = (float*)(w2_s + W2_U64);                         // 84KB
    float* fi_s   = xstage + XSTG_FLOATS;                            // 2048
    float* fo_s   = fi_s + DDIM;                                     // 16
    float* b_s    = fo_s + NEXP;                                     // 16
    float* z_s    = b_s + NEXP;                                      // 14

    // --- noise factors ---
    for (int i = threadIdx.x; i < DDIM; i += BLOCK_MAIN) fi_s[i] = fnoise(ei[i]);
    if (threadIdx.x < NEXP) {
        float fo = fnoise(eo[threadIdx.x]);
        fo_s[threadIdx.x] = fo;
        b_s[threadIdx.x] = b[threadIdx.x] + sb[threadIdx.x] * fo;
    }
    __syncthreads();

    // --- noisy weights into window/e_local/lane layout (d-pair packed) ---
    for (int it = threadIdx.x; it < NEXP * (DDIM / 2); it += BLOCK_MAIN) {
        int e = it >> 10;              // expert
        int d = (it & 1023) * 2;       // even d
        float2 wv = *(const float2*)(w  + e * DDIM + d);
        float2 sv = *(const float2*)(sw + e * DDIM + d);
        float2 fi = *(const float2*)(fi_s + d);
        float fo = fo_s[e];
        float a0 = wv.x + sv.x * fo * fi.x;
        float a1 = wv.y + sv.y * fo * fi.y;
        int wi = d >> 5, el = e & 3, q = e >> 2;
        int j = (d >> 2) & 7, k = (d >> 1) & 1;
        w2_s[wi * 256 + el * 64 + (q * 8 + j) * 2 + k] = pack2(a0, a1);
    }
    __syncthreads();

    const int lane = threadIdx.x & 31;
    const int wid  = threadIdx.x >> 5;
    const int gw   = blockIdx.x * WARPS_CTA + wid;   // group id == warp id
    const int j8   = lane & 7;                       // d-slot within window
    const int q4   = lane >> 3;                      // quarter (expert group)

    float* warp_stg = xstage + wid * (STAGES * STG_FLOATS);
    float* idx_out  = out + (size_t)NTOK * NEXP;

    if (gw < NGRP) {
        const int t0 = gw * TOK_W;
        const float* xg = x + (size_t)t0 * DDIM;
        unsigned stg_u32 = smem_u32(warp_stg);

        // prime 3 stages with half-chunks 0..2
        // slot = t*16 + s4 (128 16B-slots per stage); call tp covers 32 slots
        #pragma unroll
        for (int s = 0; s < STAGES; s++) {
            #pragma unroll
            for (int tp = 0; tp < 4; tp++) {
                int slot = tp * 32 + lane;
                int t = slot >> 4, s4 = slot & 15;
                cp16(stg_u32 + s * 2048 + slot * 16,
                     xg + t * DDIM + s * 64 + s4 * 4);
            }
            cp_commit();
        }

        u64 acc[TOK_W][4];
        #pragma unroll
        for (int t = 0; t < TOK_W; t++)
            #pragma unroll
            for (int el = 0; el < 4; el++) acc[t][el] = 0ULL;

        int stage = 0;
        #pragma unroll 1
        for (int hc = 0; hc < NHC; hc++) {
            cp_wait2();   // half-chunk hc resident

            #pragma unroll
            for (int sub = 0; sub < 2; sub++) {
                const int wi = hc * 2 + sub;
                // hoist w for this 32-d window: 4 conflict-free LDS.128
                const u64* wb = w2_s + wi * 256 + lane * 2;
                u64 wv[4][2];
                #pragma unroll
                for (int el = 0; el < 4; el++) {
                    ulonglong2 u = *(const ulonglong2*)(wb + el * 64);
                    wv[el][0] = u.x;   // (w[d],   w[d+1])
                    wv[el][1] = u.y;   // (w[d+2], w[d+3])
                }
                const float* xs = warp_stg + stage * STG_FLOATS + sub * 32 + j8 * 4;
                #pragma unroll
                for (int t = 0; t < TOK_W; t++) {
                    ulonglong2 xu = *(const ulonglong2*)(xs + t * 64);
                    #pragma unroll
                    for (int el = 0; el < 4; el++) {
                        ffma2(acc[t][el], xu.x, wv[el][0]);
                        ffma2(acc[t][el], xu.y, wv[el][1]);
                    }
                }
            }

            // refill this stage with half-chunk hc+3
            if (hc < NHC - STAGES) {
                #pragma unroll
                for (int tp = 0; tp < 4; tp++) {
                    int slot = tp * 32 + lane;
                    int t = slot >> 4, s4 = slot & 15;
                    cp16(stg_u32 + stage * 2048 + slot * 16,
                         xg + t * DDIM + (hc + 3) * 64 + s4 * 4);
                }
            }
            cp_commit();   // uniform commit keeps wait_group algebra exact
            stage = (stage == STAGES - 1) ? 0 : stage + 1;
        }
        cp_wait0();   // drain before reusing the stage as scratch

        // butterfly within each 8-lane quarter, then even+odd horizontal add
        float fs[TOK_W][4];
        #pragma unroll
        for (int t = 0; t < TOK_W; t++)
            #pragma unroll
            for (int el = 0; el < 4; el++) {
                u64 s = acc[t][el];
                s = addx2(s, __shfl_xor_sync(0xffffffffu, s, 4));
                s = addx2(s, __shfl_xor_sync(0xffffffffu, s, 2));
                s = addx2(s, __shfl_xor_sync(0xffffffffu, s, 1));
                float2 qv = unpack64(s);
                fs[t][el] = qv.x + qv.y;
            }

        // cross-quarter exchange through this warp's retired stage memory
        // red[t*16 + e] ; quarter q lane j8==0 writes its 4 experts per token
        float* red = warp_stg;           // 128 floats used
        if (j8 == 0) {
            #pragma unroll
            for (int t = 0; t < TOK_W; t++)
                *(float4*)(red + t * 16 + q4 * 4) =
                    make_float4(fs[t][0], fs[t][1], fs[t][2], fs[t][3]);
        }
        __syncwarp();

        const int town = lane >> 2;      // this lane's token
        const int qq   = lane & 3;       // this lane's 4-expert output slice
        float v[NEXP];
        #pragma unroll
        for (int g2 = 0; g2 < 4; g2++) {
            float4 u = *(const float4*)(red + town * 16 + g2 * 4);
            v[g2 * 4 + 0] = u.x;
            v[g2 * 4 + 1] = u.y;
            v[g2 * 4 + 2] = u.z;
            v[g2 * 4 + 3] = u.w;
        }

        // top-2 + softmax + z for this lane's token
        float m1 = -1e30f, m2 = -1e30f;
        int i1 = 0, i2 = 0;
        #pragma unroll
        for (int e = 0; e < NEXP; e++) {
            float le = v[e] + b_s[e];
            if (le > m1)      { m2 = m1; i2 = i1; m1 = le; i1 = e; }
            else if (le > m2) { m2 = le; i2 = e; }
        }
        float ez = __expf(m2 - m1);
        float rz = 1.0f / (1.0f + ez);
        float p1 = rz, p2 = ez * rz;

        const int tok = t0 + town;
        const int e0 = qq * 4;
        float4 o4;
        o4.x = (e0 + 0 == i1) ? p1 : ((e0 + 0 == i2) ? p2 : 0.0f);
        o4.y = (e0 + 1 == i1) ? p1 : ((e0 + 1 == i2) ? p2 : 0.0f);
        o4.z = (e0 + 2 == i1) ? p1 : ((e0 + 2 == i2) ? p2 : 0.0f);
        o4.w = (e0 + 3 == i1) ? p1 : ((e0 + 3 == i2) ? p2 : 0.0f);
        *(float4*)(out + (size_t)tok * NEXP + e0) = o4;
        if (qq == 0)
            *(float2*)(idx_out + (size_t)tok * 2) =
                make_float2((float)i1, (float)i2);

        float lse = m1 + log1pf(ez);
        float zl = (qq == 0) ? lse * lse : 0.0f;
        #pragma unroll
        for (int k = 16; k > 0; k >>= 1)
            zl += __shfl_xor_sync(0xffffffffu, zl, k);
        if (lane == 0) z_s[wid] = zl;
    } else {
        if (lane == 0) z_s[wid] = 0.0f;
    }

    // --- fused z-loss reduction: CTA partial, then last CTA finishes ---
    __syncthreads();
    __shared__ unsigned int s_last;
    if (threadIdx.x == 0) {
        float a = 0.0f;
        #pragma unroll
        for (int i = 0; i < WARPS_CTA; i++) a += z_s[i];
        g_zp[blockIdx.x] = a;
        __threadfence();
        unsigned int ticket = atomicAdd(&g_ctr, 1u);
        s_last = (ticket == GRID_MAIN - 1) ? 1u : 0u;
    }
    __syncthreads();
    if (s_last && wid == 0) {
        float a = 0.0f;
        for (int i = lane; i < GRID_MAIN; i += 32) a += __ldcg(&g_zp[i]);
        #pragma unroll
        for (int k = 16; k > 0; k >>= 1)
            a += __shfl_xor_sync(0xffffffffu, a, k);
        if (lane == 0) {
            out[(size_t)NTOK * NEXP + (size_t)NTOK * 2] = a * (1.0f / (float)NTOK);
            g_ctr = 0;   // reset for next launch / graph replay
        }
    }
}

// ---------------------------------------------------------------------------
extern "C" void kernel_launch(void* const* d_in, const int* in_sizes, int n_in,
                              void* d_out, int out_size) {
    const float* x  = (const float*)d_in[0];  // mh_output [4,4096,2048]
    const float* w  = (const float*)d_in[1];  // weight [16,2048]
    const float* sw = (const float*)d_in[2];  // sigma_weight
    const float* b  = (const float*)d_in[3];  // bias [16]
    const float* sb = (const float*)d_in[4];  // sigma_bias
    const float* ei = (const float*)d_in[5];  // eps_in [2048]
    const float* eo = (const float*)d_in[6];  // eps_out [16]
    float* out = (float*)d_out;

    const size_t smem_bytes = (size_t)W2_U64 * 8
                            + (size_t)XSTG_FLOATS * 4
                            + (size_t)(DDIM + 2 * NEXP + WARPS_CTA) * sizeof(float)
                            + 64;
    cudaFuncSetAttribute(router_kernel,
                         cudaFuncAttributeMaxDynamicSharedMemorySize,
                         (int)smem_bytes);
    router_kernel<<<GRID_MAIN, BLOCK_MAIN, smem_bytes>>>(x, w, sw, b, sb, ei, eo, out);
}